// round 12
// baseline (speedup 1.0000x reference)
#include <cuda_runtime.h>
#include <cuda_bf16.h>
#include <math.h>
#include <stdint.h>

// Problem constants (fixed shapes: L=5, B=8, n=1024, d=64)
#define LNUM 5
#define BNUM 8
#define NLB  40
#define N    1024
#define D    64
#define S    16                  // n-dim chunks (64 rows each)
#define KR   64                  // n-rows per chunk
#define KB   128                 // bf16 K rows (hi + lo)
#define PITCH  72                // bf16 units per T row (pad: conflict-free ldmatrix)
#define PITCHB 144               // bytes per T row
#define GSZ  4096
#define STRIDE (3 * GSZ + 2 * D) // per-chunk scratch: XX, YY, XY, sx, sy

__device__ float g_part[NLB * S * STRIDE];   // ~31.8 MB scratch
__device__ float g_sums[NLB * 8 * 3];

#define T_BYTES  (KB * PITCHB)       // 18432
#define SMEM_DYN (2 * T_BYTES)       // 36864

__device__ __forceinline__ uint32_t smem_u32(const void* p) {
    uint32_t a;
    asm("{ .reg .u64 t; cvta.to.shared.u64 t, %1; cvt.u32.u64 %0, t; }" : "=r"(a) : "l"(p));
    return a;
}

// ldmatrix x4 transposed (b16): pairs run along the k (row) dimension of T
#define LDSM4T(r, a) \
    asm volatile("ldmatrix.sync.aligned.m8n8.x4.trans.shared.b16 {%0,%1,%2,%3}, [%4];" \
        : "=r"((r)[0]), "=r"((r)[1]), "=r"((r)[2]), "=r"((r)[3]) : "r"(a))

// D += A * B  (m16n8k16, bf16 in, f32 accumulate)
#define MMA_BF16(c, a, b0, b1) \
    asm volatile("mma.sync.aligned.m16n8k16.row.col.f32.bf16.bf16.f32 " \
        "{%0,%1,%2,%3}, {%4,%5,%6,%7}, {%8,%9}, {%0,%1,%2,%3};" \
        : "+f"((c)[0]), "+f"((c)[1]), "+f"((c)[2]), "+f"((c)[3]) \
        : "r"((a)[0]), "r"((a)[1]), "r"((a)[2]), "r"((a)[3]), "r"(b0), "r"(b1))

// ---------------------------------------------------------------------------
// Kernel A: per (lb, 64-row chunk) Grams XtX, YtY, XtY via bf16 hi/lo
// mma.sync. T = [hi(M); lo(M)] : 128 x 64 bf16, pitch 72.
// 4 warps; warp w owns gram rows 16w..16w+15, full n=64.
// grid = 40*16 = 640 blocks, 128 threads, 4 blocks/SM (latency hiding).
// ---------------------------------------------------------------------------
__global__ void __launch_bounds__(128, 4) cka_gram_kernel(
    const float* __restrict__ Xg, const float* __restrict__ Yg)
{
    extern __shared__ char smem[];
    char* Tx = smem;
    char* Ty = smem + T_BYTES;
    const int tid = threadIdx.x;
    const int w = tid >> 5, l = tid & 31;
    const int lb = blockIdx.x >> 4, ks = blockIdx.x & 15;

    const float* xb = Xg + (size_t)lb * N * D + (size_t)ks * KR * D;
    const float* yb = Yg + (size_t)lb * N * D + (size_t)ks * KR * D;

    // ---- load + hi/lo bf16 convert into T tiles ----
    #pragma unroll
    for (int mat = 0; mat < 2; ++mat) {
        const float4* g4 = (const float4*)(mat ? yb : xb);
        char* T = mat ? Ty : Tx;
        #pragma unroll
        for (int it = 0; it < 8; ++it) {
            int idx = tid + 128 * it;
            int n = idx >> 4, dq = idx & 15;
            float4 v = g4[idx];
            uint32_t h01, h23, l01, l23;
            asm("cvt.rn.bf16x2.f32 %0, %1, %2;" : "=r"(h01) : "f"(v.y), "f"(v.x));
            asm("cvt.rn.bf16x2.f32 %0, %1, %2;" : "=r"(h23) : "f"(v.w), "f"(v.z));
            float r0 = v.x - __uint_as_float(h01 << 16);
            float r1 = v.y - __uint_as_float(h01 & 0xffff0000u);
            float r2 = v.z - __uint_as_float(h23 << 16);
            float r3 = v.w - __uint_as_float(h23 & 0xffff0000u);
            asm("cvt.rn.bf16x2.f32 %0, %1, %2;" : "=r"(l01) : "f"(r1), "f"(r0));
            asm("cvt.rn.bf16x2.f32 %0, %1, %2;" : "=r"(l23) : "f"(r3), "f"(r2));
            uint2 hv; hv.x = h01; hv.y = h23;
            uint2 lv; lv.x = l01; lv.y = l23;
            *(uint2*)(T + n * PITCHB + 8 * dq) = hv;           // hi rows 0..63
            *(uint2*)(T + (n + KR) * PITCHB + 8 * dq) = lv;    // lo rows 64..127
        }
    }
    __syncthreads();

    float* out = g_part + (size_t)(lb * S + ks) * STRIDE;

    // ---- column sums (hi + lo rows sum == chunk col sum to 2^-17) ----
    if (tid < 64) {
        int p = tid & 31;                       // col pair {2p, 2p+1}
        const char* T = (tid < 32) ? Tx : Ty;
        float s0 = 0.f, s1 = 0.f;
        #pragma unroll 8
        for (int r = 0; r < KB; ++r) {
            uint32_t u = *(const uint32_t*)(T + r * PITCHB + 4 * p);
            s0 += __uint_as_float(u << 16);
            s1 += __uint_as_float(u & 0xffff0000u);
        }
        float* o = out + 3 * GSZ + ((tid < 32) ? 0 : 64) + 2 * p;
        o[0] = s0;
        o[1] = s1;
    }

    // ---- MMA mainloop ----
    const uint32_t sTx = smem_u32(Tx), sTy = smem_u32(Ty);
    const int g = l >> 3, ri = l & 7;
    const uint32_t offA = (uint32_t)((((g >> 1) & 1) * 8 + ri) * PITCHB
                                     + (g & 1) * 16 + (16 * w) * 2);
    const uint32_t offB = (uint32_t)(((g & 1) * 8 + ri) * PITCHB
                                     + ((g >> 1) & 1) * 16);

    float cXX[8][4] = {}, cXY[8][4] = {}, cYY[8][4] = {};

    #pragma unroll
    for (int kk = 0; kk < KB / 16; ++kk) {
        uint32_t kb = (uint32_t)(kk * 16 * PITCHB);
        uint32_t ax[4], ay[4];
        LDSM4T(ax, sTx + offA + kb);
        LDSM4T(ay, sTy + offA + kb);
        #pragma unroll
        for (int nt = 0; nt < 4; ++nt) {
            uint32_t bx[4], by[4];
            LDSM4T(bx, sTx + offB + kb + 32 * nt);
            LDSM4T(by, sTy + offB + kb + 32 * nt);
            MMA_BF16(cXX[2 * nt],     ax, bx[0], bx[1]);
            MMA_BF16(cXX[2 * nt + 1], ax, bx[2], bx[3]);
            MMA_BF16(cXY[2 * nt],     ax, by[0], by[1]);
            MMA_BF16(cXY[2 * nt + 1], ax, by[2], by[3]);
            MMA_BF16(cYY[2 * nt],     ay, by[0], by[1]);
            MMA_BF16(cYY[2 * nt + 1], ay, by[2], by[3]);
        }
    }

    // ---- epilogue: c-frag -> g_part ----
    {
        int r0 = 16 * w + (l >> 2);
        int c0 = 2 * (l & 3);
        #pragma unroll
        for (int f = 0; f < 8; ++f) {
            int col = 8 * f + c0;
            float2 v;
            v.x = cXX[f][0]; v.y = cXX[f][1];
            *(float2*)(out + r0 * 64 + col) = v;
            v.x = cXX[f][2]; v.y = cXX[f][3];
            *(float2*)(out + (r0 + 8) * 64 + col) = v;
            v.x = cYY[f][0]; v.y = cYY[f][1];
            *(float2*)(out + GSZ + r0 * 64 + col) = v;
            v.x = cYY[f][2]; v.y = cYY[f][3];
            *(float2*)(out + GSZ + (r0 + 8) * 64 + col) = v;
            v.x = cXY[f][0]; v.y = cXY[f][1];
            *(float2*)(out + 2 * GSZ + r0 * 64 + col) = v;
            v.x = cXY[f][2]; v.y = cXY[f][3];
            *(float2*)(out + 2 * GSZ + (r0 + 8) * 64 + col) = v;
        }
    }
}

// ---------------------------------------------------------------------------
// Kernel B: per (lb, slice-of-8) reduce S chunk-partials, apply rank-1
// centering correction, partial Frobenius-square-reduce.
// ---------------------------------------------------------------------------
__global__ void __launch_bounds__(128) cka_reduce_kernel()
{
    const int lb = blockIdx.x >> 3;
    const int slice = blockIdx.x & 7;
    const int tid = threadIdx.x;
    __shared__ float sx[D], sy[D];
    __shared__ float red[128];

    const float* base = g_part + (size_t)lb * S * STRIDE;

    if (tid < 64) {
        float ax = 0.f, ay = 0.f;
        #pragma unroll
        for (int s = 0; s < S; ++s) {
            ax += base[s * STRIDE + 3 * GSZ + tid];
            ay += base[s * STRIDE + 3 * GSZ + 64 + tid];
        }
        sx[tid] = ax;
        sy[tid] = ay;
    }
    __syncthreads();

    const float inv_n = 1.0f / (float)N;
    const int f4i = slice * 128 + tid;
    const int i = f4i >> 4;
    const int jb = (f4i & 15) * 4;

    const float sxi = sx[i] * inv_n;
    const float syi = sy[i] * inv_n;
    const float4 sxj = *(const float4*)&sx[jb];
    const float4 syj = *(const float4*)&sy[jb];

    float4 gxx = {0, 0, 0, 0}, gyy = {0, 0, 0, 0}, gxy = {0, 0, 0, 0};
    #pragma unroll
    for (int s = 0; s < S; ++s) {
        const float4* p = (const float4*)(base + (size_t)s * STRIDE);
        float4 v;
        v = p[f4i];
        gxx.x += v.x; gxx.y += v.y; gxx.z += v.z; gxx.w += v.w;
        v = p[1024 + f4i];
        gyy.x += v.x; gyy.y += v.y; gyy.z += v.z; gyy.w += v.w;
        v = p[2048 + f4i];
        gxy.x += v.x; gxy.y += v.y; gxy.z += v.z; gxy.w += v.w;
    }

    gxx.x -= sxi * sxj.x; gxx.y -= sxi * sxj.y; gxx.z -= sxi * sxj.z; gxx.w -= sxi * sxj.w;
    gyy.x -= syi * syj.x; gyy.y -= syi * syj.y; gyy.z -= syi * syj.z; gyy.w -= syi * syj.w;
    gxy.x -= sxi * syj.x; gxy.y -= sxi * syj.y; gxy.z -= sxi * syj.z; gxy.w -= sxi * syj.w;

    float vXX = gxx.x * gxx.x + gxx.y * gxx.y + gxx.z * gxx.z + gxx.w * gxx.w;
    float vYY = gyy.x * gyy.x + gyy.y * gyy.y + gyy.z * gyy.z + gyy.w * gyy.w;
    float vXY = gxy.x * gxy.x + gxy.y * gxy.y + gxy.z * gxy.z + gxy.w * gxy.w;

    float* gs = g_sums + (size_t)(lb * 8 + slice) * 3;

    red[tid] = vXX;
    __syncthreads();
    for (int off = 64; off > 0; off >>= 1) {
        if (tid < off) red[tid] += red[tid + off];
        __syncthreads();
    }
    if (tid == 0) gs[0] = red[0];
    __syncthreads();

    red[tid] = vYY;
    __syncthreads();
    for (int off = 64; off > 0; off >>= 1) {
        if (tid < off) red[tid] += red[tid + off];
        __syncthreads();
    }
    if (tid == 0) gs[1] = red[0];
    __syncthreads();

    red[tid] = vXY;
    __syncthreads();
    for (int off = 64; off > 0; off >>= 1) {
        if (tid < off) red[tid] += red[tid + off];
        __syncthreads();
    }
    if (tid == 0) gs[2] = red[0];
}

// ---------------------------------------------------------------------------
// Kernel C: final scalar loss = mean_l( -log( mean_b ratio + eps ) )
// ---------------------------------------------------------------------------
__global__ void cka_final_kernel(float* __restrict__ out)
{
    __shared__ float ratio[NLB];
    const int tid = threadIdx.x;
    if (tid < NLB) {
        float txx = 0.f, tyy = 0.f, txy = 0.f;
        #pragma unroll
        for (int s2 = 0; s2 < 8; ++s2) {
            const float* g = g_sums + (size_t)(tid * 8 + s2) * 3;
            txx += g[0];
            tyy += g[1];
            txy += g[2];
        }
        ratio[tid] = fabsf(txy) / (sqrtf(txx) * sqrtf(tyy));
    }
    __syncthreads();
    if (tid == 0) {
        float loss = 0.f;
        #pragma unroll
        for (int l = 0; l < LNUM; ++l) {
            float m = 0.f;
            #pragma unroll
            for (int b = 0; b < BNUM; ++b)
                m += ratio[l * BNUM + b];
            m *= (1.0f / (float)BNUM);
            loss += -logf(m + 1e-8f);
        }
        out[0] = loss * (1.0f / (float)LNUM);
    }
}

extern "C" void kernel_launch(void* const* d_in, const int* in_sizes, int n_in,
                              void* d_out, int out_size)
{
    const float* teacher = (const float*)d_in[0];
    const float* student = (const float*)d_in[1];
    float* out = (float*)d_out;

    cudaFuncSetAttribute(cka_gram_kernel,
                         cudaFuncAttributeMaxDynamicSharedMemorySize, SMEM_DYN);
    cka_gram_kernel<<<NLB * S, 128, SMEM_DYN>>>(teacher, student);
    cka_reduce_kernel<<<NLB * 8, 128>>>();
    cka_final_kernel<<<1, 64>>>(out);
}

// round 13
// speedup vs baseline: 1.3384x; 1.3384x over previous
#include <cuda_runtime.h>
#include <cuda_bf16.h>
#include <math.h>
#include <stdint.h>

// Problem constants (fixed shapes: L=5, B=8, n=1024, d=64)
#define LNUM 5
#define BNUM 8
#define NLB  40
#define N    1024
#define D    64
#define S    8                   // n-dim chunks (128 rows each)
#define KR   128                 // n-rows per chunk = bf16 K rows (hi only)
#define KB   128
#define PITCH  72                // bf16 units per T row (pad: conflict-free ldmatrix)
#define PITCHB 144               // bytes per T row
#define GSZ  4096
#define STRIDE (3 * GSZ + 2 * D) // per-chunk scratch: XX, YY, XY, sx, sy

__device__ float g_part[NLB * S * STRIDE];   // ~15.9 MB scratch
__device__ float g_sums[NLB * 8 * 3];

#define T_BYTES  (KB * PITCHB)             // 18432
#define CR_OFF   (2 * T_BYTES)             // colsum reduce scratch
#define SMEM_DYN (2 * T_BYTES + 4096)      // 40960

__device__ __forceinline__ uint32_t smem_u32(const void* p) {
    uint32_t a;
    asm("{ .reg .u64 t; cvta.to.shared.u64 t, %1; cvt.u32.u64 %0, t; }" : "=r"(a) : "l"(p));
    return a;
}

// ldmatrix x4 transposed (b16): pairs run along the k (row) dimension of T
#define LDSM4T(r, a) \
    asm volatile("ldmatrix.sync.aligned.m8n8.x4.trans.shared.b16 {%0,%1,%2,%3}, [%4];" \
        : "=r"((r)[0]), "=r"((r)[1]), "=r"((r)[2]), "=r"((r)[3]) : "r"(a))

// D += A * B  (m16n8k16, bf16 in, f32 accumulate)
#define MMA_BF16(c, a, b0, b1) \
    asm volatile("mma.sync.aligned.m16n8k16.row.col.f32.bf16.bf16.f32 " \
        "{%0,%1,%2,%3}, {%4,%5,%6,%7}, {%8,%9}, {%0,%1,%2,%3};" \
        : "+f"((c)[0]), "+f"((c)[1]), "+f"((c)[2]), "+f"((c)[3]) \
        : "r"((a)[0]), "r"((a)[1]), "r"((a)[2]), "r"((a)[3]), "r"(b0), "r"(b1))

// ---------------------------------------------------------------------------
// Kernel A: per (lb, 128-row chunk) Grams XtX, YtY, XtY via bf16 (hi-only)
// mma.sync, K=128. T : 128 x 64 bf16, pitch 72. Column sums accumulated in
// exact fp32 from the input registers during convert.
// 4 warps; warp w owns gram rows 16w..16w+15, full n=64.
// grid = 40*8 = 320 blocks, 128 threads.
// ---------------------------------------------------------------------------
__global__ void __launch_bounds__(128) cka_gram_kernel(
    const float* __restrict__ Xg, const float* __restrict__ Yg)
{
    extern __shared__ char smem[];
    char* Tx = smem;
    char* Ty = smem + T_BYTES;
    float4* colred = (float4*)(smem + CR_OFF);   // [mat][dq 0..15][grp 0..7]
    const int tid = threadIdx.x;
    const int w = tid >> 5, l = tid & 31;
    const int lb = blockIdx.x >> 3, ks = blockIdx.x & 7;
    const int dq = tid & 15, grp = tid >> 4;     // convert-loop coords

    const float* xb = Xg + (size_t)lb * N * D + (size_t)ks * KR * D;
    const float* yb = Yg + (size_t)lb * N * D + (size_t)ks * KR * D;

    // ---- load + bf16 convert (hi only) + fp32 colsum partials ----
    float4 csx = {0, 0, 0, 0}, csy = {0, 0, 0, 0};
    #pragma unroll
    for (int mat = 0; mat < 2; ++mat) {
        const float4* g4 = (const float4*)(mat ? yb : xb);
        char* T = mat ? Ty : Tx;
        float4* cs = mat ? &csy : &csx;
        #pragma unroll
        for (int it = 0; it < 16; ++it) {
            int idx = tid + 128 * it;
            int n = idx >> 4;                    // row; dq is per-thread fixed
            float4 v = g4[idx];
            cs->x += v.x; cs->y += v.y; cs->z += v.z; cs->w += v.w;
            uint32_t h01, h23;
            asm("cvt.rn.bf16x2.f32 %0, %1, %2;" : "=r"(h01) : "f"(v.y), "f"(v.x));
            asm("cvt.rn.bf16x2.f32 %0, %1, %2;" : "=r"(h23) : "f"(v.w), "f"(v.z));
            uint2 hv; hv.x = h01; hv.y = h23;
            *(uint2*)(T + n * PITCHB + 8 * dq) = hv;
        }
    }
    colred[(0 * 16 + dq) * 8 + grp] = csx;
    colred[(1 * 16 + dq) * 8 + grp] = csy;
    __syncthreads();

    float* out = g_part + (size_t)(lb * S + ks) * STRIDE;

    // ---- colsum reduce: 32 threads, each sums 8 float4 partials ----
    if (tid < 32) {
        const float4* p = colred + tid * 8;
        float4 s = p[0];
        #pragma unroll
        for (int g2 = 1; g2 < 8; ++g2) {
            float4 v = p[g2];
            s.x += v.x; s.y += v.y; s.z += v.z; s.w += v.w;
        }
        // tid = mat*16 + dqq -> cols 4dqq..4dqq+3 of mat
        *(float4*)(out + 3 * GSZ + (tid >> 4) * 64 + (tid & 15) * 4) = s;
    }

    // ---- MMA mainloop (K = 128) ----
    const uint32_t sTx = smem_u32(Tx), sTy = smem_u32(Ty);
    const int g = l >> 3, ri = l & 7;
    const uint32_t offA = (uint32_t)((((g >> 1) & 1) * 8 + ri) * PITCHB
                                     + (g & 1) * 16 + (16 * w) * 2);
    const uint32_t offB = (uint32_t)(((g & 1) * 8 + ri) * PITCHB
                                     + ((g >> 1) & 1) * 16);

    float cXX[8][4] = {}, cXY[8][4] = {}, cYY[8][4] = {};

    #pragma unroll
    for (int kk = 0; kk < KB / 16; ++kk) {
        uint32_t kb = (uint32_t)(kk * 16 * PITCHB);
        uint32_t ax[4], ay[4];
        LDSM4T(ax, sTx + offA + kb);
        LDSM4T(ay, sTy + offA + kb);
        #pragma unroll
        for (int nt = 0; nt < 4; ++nt) {
            uint32_t bx[4], by[4];
            LDSM4T(bx, sTx + offB + kb + 32 * nt);
            LDSM4T(by, sTy + offB + kb + 32 * nt);
            MMA_BF16(cXX[2 * nt],     ax, bx[0], bx[1]);
            MMA_BF16(cXX[2 * nt + 1], ax, bx[2], bx[3]);
            MMA_BF16(cXY[2 * nt],     ax, by[0], by[1]);
            MMA_BF16(cXY[2 * nt + 1], ax, by[2], by[3]);
            MMA_BF16(cYY[2 * nt],     ay, by[0], by[1]);
            MMA_BF16(cYY[2 * nt + 1], ay, by[2], by[3]);
        }
    }

    // ---- epilogue: c-frag -> g_part ----
    {
        int r0 = 16 * w + (l >> 2);
        int c0 = 2 * (l & 3);
        #pragma unroll
        for (int f = 0; f < 8; ++f) {
            int col = 8 * f + c0;
            float2 v;
            v.x = cXX[f][0]; v.y = cXX[f][1];
            *(float2*)(out + r0 * 64 + col) = v;
            v.x = cXX[f][2]; v.y = cXX[f][3];
            *(float2*)(out + (r0 + 8) * 64 + col) = v;
            v.x = cYY[f][0]; v.y = cYY[f][1];
            *(float2*)(out + GSZ + r0 * 64 + col) = v;
            v.x = cYY[f][2]; v.y = cYY[f][3];
            *(float2*)(out + GSZ + (r0 + 8) * 64 + col) = v;
            v.x = cXY[f][0]; v.y = cXY[f][1];
            *(float2*)(out + 2 * GSZ + r0 * 64 + col) = v;
            v.x = cXY[f][2]; v.y = cXY[f][3];
            *(float2*)(out + 2 * GSZ + (r0 + 8) * 64 + col) = v;
        }
    }
}

// ---------------------------------------------------------------------------
// Kernel B: per (lb, slice-of-8) reduce S chunk-partials, apply rank-1
// centering correction, partial Frobenius-square-reduce.
// ---------------------------------------------------------------------------
__global__ void __launch_bounds__(128) cka_reduce_kernel()
{
    const int lb = blockIdx.x >> 3;
    const int slice = blockIdx.x & 7;
    const int tid = threadIdx.x;
    __shared__ float sx[D], sy[D];
    __shared__ float red[128];

    const float* base = g_part + (size_t)lb * S * STRIDE;

    if (tid < 64) {
        float ax = 0.f, ay = 0.f;
        #pragma unroll
        for (int s = 0; s < S; ++s) {
            ax += base[s * STRIDE + 3 * GSZ + tid];
            ay += base[s * STRIDE + 3 * GSZ + 64 + tid];
        }
        sx[tid] = ax;
        sy[tid] = ay;
    }
    __syncthreads();

    const float inv_n = 1.0f / (float)N;
    const int f4i = slice * 128 + tid;
    const int i = f4i >> 4;
    const int jb = (f4i & 15) * 4;

    const float sxi = sx[i] * inv_n;
    const float syi = sy[i] * inv_n;
    const float4 sxj = *(const float4*)&sx[jb];
    const float4 syj = *(const float4*)&sy[jb];

    float4 gxx = {0, 0, 0, 0}, gyy = {0, 0, 0, 0}, gxy = {0, 0, 0, 0};
    #pragma unroll
    for (int s = 0; s < S; ++s) {
        const float4* p = (const float4*)(base + (size_t)s * STRIDE);
        float4 v;
        v = p[f4i];
        gxx.x += v.x; gxx.y += v.y; gxx.z += v.z; gxx.w += v.w;
        v = p[1024 + f4i];
        gyy.x += v.x; gyy.y += v.y; gyy.z += v.z; gyy.w += v.w;
        v = p[2048 + f4i];
        gxy.x += v.x; gxy.y += v.y; gxy.z += v.z; gxy.w += v.w;
    }

    gxx.x -= sxi * sxj.x; gxx.y -= sxi * sxj.y; gxx.z -= sxi * sxj.z; gxx.w -= sxi * sxj.w;
    gyy.x -= syi * syj.x; gyy.y -= syi * syj.y; gyy.z -= syi * syj.z; gyy.w -= syi * syj.w;
    gxy.x -= sxi * syj.x; gxy.y -= sxi * syj.y; gxy.z -= sxi * syj.z; gxy.w -= sxi * syj.w;

    float vXX = gxx.x * gxx.x + gxx.y * gxx.y + gxx.z * gxx.z + gxx.w * gxx.w;
    float vYY = gyy.x * gyy.x + gyy.y * gyy.y + gyy.z * gyy.z + gyy.w * gyy.w;
    float vXY = gxy.x * gxy.x + gxy.y * gxy.y + gxy.z * gxy.z + gxy.w * gxy.w;

    float* gs = g_sums + (size_t)(lb * 8 + slice) * 3;

    red[tid] = vXX;
    __syncthreads();
    for (int off = 64; off > 0; off >>= 1) {
        if (tid < off) red[tid] += red[tid + off];
        __syncthreads();
    }
    if (tid == 0) gs[0] = red[0];
    __syncthreads();

    red[tid] = vYY;
    __syncthreads();
    for (int off = 64; off > 0; off >>= 1) {
        if (tid < off) red[tid] += red[tid + off];
        __syncthreads();
    }
    if (tid == 0) gs[1] = red[0];
    __syncthreads();

    red[tid] = vXY;
    __syncthreads();
    for (int off = 64; off > 0; off >>= 1) {
        if (tid < off) red[tid] += red[tid + off];
        __syncthreads();
    }
    if (tid == 0) gs[2] = red[0];
}

// ---------------------------------------------------------------------------
// Kernel C: final scalar loss = mean_l( -log( mean_b ratio + eps ) )
// ---------------------------------------------------------------------------
__global__ void cka_final_kernel(float* __restrict__ out)
{
    __shared__ float ratio[NLB];
    const int tid = threadIdx.x;
    if (tid < NLB) {
        float txx = 0.f, tyy = 0.f, txy = 0.f;
        #pragma unroll
        for (int s2 = 0; s2 < 8; ++s2) {
            const float* g = g_sums + (size_t)(tid * 8 + s2) * 3;
            txx += g[0];
            tyy += g[1];
            txy += g[2];
        }
        ratio[tid] = fabsf(txy) / (sqrtf(txx) * sqrtf(tyy));
    }
    __syncthreads();
    if (tid == 0) {
        float loss = 0.f;
        #pragma unroll
        for (int l = 0; l < LNUM; ++l) {
            float m = 0.f;
            #pragma unroll
            for (int b = 0; b < BNUM; ++b)
                m += ratio[l * BNUM + b];
            m *= (1.0f / (float)BNUM);
            loss += -logf(m + 1e-8f);
        }
        out[0] = loss * (1.0f / (float)LNUM);
    }
}

extern "C" void kernel_launch(void* const* d_in, const int* in_sizes, int n_in,
                              void* d_out, int out_size)
{
    const float* teacher = (const float*)d_in[0];
    const float* student = (const float*)d_in[1];
    float* out = (float*)d_out;

    cudaFuncSetAttribute(cka_gram_kernel,
                         cudaFuncAttributeMaxDynamicSharedMemorySize, SMEM_DYN);
    cka_gram_kernel<<<NLB * S, 128, SMEM_DYN>>>(teacher, student);
    cka_reduce_kernel<<<NLB * 8, 128>>>();
    cka_final_kernel<<<1, 64>>>(out);
}